// round 8
// baseline (speedup 1.0000x reference)
#include <cuda_runtime.h>
#include <cuda_fp16.h>
#include <math.h>

#define BATCH 16
#define CH    64
#define NPIX  25600          // 160*160
#define HID   256
#define KSEL  20480          // ceil(25600*0.8)
#define TOKB  256            // tokens per block
#define NTHR  256            // 8 warps x 32 tokens each

#define ST_S  68             // sT fp32 row stride (272B)
#define W1_S  136            // fp16 elements per row (272B), chunk rows=64
#define W2_S  72             // fp16 elements per row (144B), chunk rows=128

// smem byte offsets (main kernel)
#define OFF_T    0            // 256*68*4 = 69632
#define OFF_W    69632        // two chunk buffers, each 35840 (W1 17408 + W2 18432)
#define BUFB     35840
#define OFF_B1   141312       // 256 u32 (h2-packed bias1)
#define OFF_B2   142336       // 2*64*4 = 512
#define OFF_LS   142848       // 512
#define OFF_LB   143360       // 512
#define OFF_FLAG 143872       // 256*4 = 1024
#define SMEM_BYTES 144896

// ---------------- static scratch ----------------
__device__ unsigned      g_thresh[BATCH];
__device__ int           g_ties[BATCH];
__device__ unsigned char g_flags[BATCH * NPIX];
// pre-converted fp16 weights in smem tile layout (chunk = layer*2 + jc)
__device__ unsigned short g_w1[4 * 64 * W1_S];
__device__ unsigned short g_w2[4 * 128 * W2_S];

__device__ __forceinline__ unsigned fkey(float f) {
    unsigned u = __float_as_uint(f);
    return (u & 0x80000000u) ? ~u : (u | 0x80000000u);
}

__device__ __forceinline__ unsigned pack_h2(float2 v) {
    __half2 h = __float22half2_rn(v);
    return *(unsigned*)&h;
}

// gelu on a packed half2 (tanh approximation, all-fp16 math)
__device__ __forceinline__ unsigned gelu_h2(unsigned vu) {
    __half2 v = *(__half2*)&vu;
    const __half2 k0  = __floats2half2_rn(0.7978845608f, 0.7978845608f);
    const __half2 k01 = __floats2half2_rn(0.0356774081f, 0.0356774081f);  // k0*0.044715
    const __half2 hf  = __floats2half2_rn(0.5f, 0.5f);
    __half2 u = __hmul2(v, v);
    __half2 w = __hmul2(u, v);
    __half2 inner = __hfma2(w, k01, __hmul2(v, k0));
    unsigned tin = *(unsigned*)&inner, tout;
    asm("tanh.approx.f16x2 %0, %1;" : "=r"(tout) : "r"(tin));
    __half2 t = *(__half2*)&tout;
    __half2 hv = __hmul2(v, hf);
    __half2 res = __hfma2(hv, t, hv);
    return *(unsigned*)&res;
}

__device__ __forceinline__ void ldsm_x4t(unsigned r[4], unsigned addr) {
    asm volatile("ldmatrix.sync.aligned.m8n8.x4.trans.shared.b16 {%0,%1,%2,%3}, [%4];"
                 : "=r"(r[0]), "=r"(r[1]), "=r"(r[2]), "=r"(r[3]) : "r"(addr));
}
__device__ __forceinline__ void mma_f16(float* d, const unsigned* a, unsigned b0, unsigned b1) {
    asm volatile("mma.sync.aligned.m16n8k16.row.col.f32.f16.f16.f32 "
                 "{%0,%1,%2,%3}, {%4,%5,%6,%7}, {%8,%9}, {%0,%1,%2,%3};"
                 : "+f"(d[0]), "+f"(d[1]), "+f"(d[2]), "+f"(d[3])
                 : "r"(a[0]), "r"(a[1]), "r"(a[2]), "r"(a[3]), "r"(b0), "r"(b1));
}
__device__ __forceinline__ void cp16(unsigned dst, const void* src) {
    asm volatile("cp.async.cg.shared.global [%0], [%1], 16;" :: "r"(dst), "l"(src));
}

// ---------------- kernel 0: pre-convert weights to fp16 (smem tile layout) --------
__global__ void prep_kernel(const float* __restrict__ w1, const float* __restrict__ w2) {
    int idx = blockIdx.x * blockDim.x + threadIdx.x;
    if (idx >= 2 * CH * HID) return;
    int layer = idx >> 14;
    int rem = idx & 16383;
    {   // w1: [layer][c][j]
        int c = rem >> 8, j = rem & 255;
        __half h = __float2half_rn(w1[idx]);
        int off = (layer * 2 + (j >> 7)) * 64 * W1_S + c * W1_S + (j & 127);
        g_w1[off] = *(unsigned short*)&h;
    }
    {   // w2: [layer][j][c]
        int j = rem >> 6, c = rem & 63;
        __half h = __float2half_rn(w2[idx]);
        int off = (layer * 2 + (j >> 7)) * 128 * W2_S + (j & 127) * W2_S + c;
        g_w2[off] = *(unsigned short*)&h;
    }
}

// ---------------- kernel 1: fused per-batch radix select + flags ----------------
__global__ void select_flags_kernel(const float* __restrict__ prop) {
    int b = blockIdx.x;
    const float* p = prop + (size_t)b * NPIX;
    extern __shared__ unsigned dyn[];
    unsigned* skey = dyn;              // 25600 keys
    unsigned* hist = dyn + NPIX;       // 256
    __shared__ unsigned s_prefix;
    __shared__ int s_k;
    __shared__ int s_carry;
    __shared__ int warp_sums[32];
    int tid = threadIdx.x;
    if (tid == 0) { s_prefix = 0u; s_k = KSEL; s_carry = 0; }
    for (int i = tid; i < NPIX; i += 1024) skey[i] = fkey(p[i]);
    __syncthreads();

    for (int pass = 3; pass >= 0; --pass) {
        int shift = pass * 8;
        if (tid < 256) hist[tid] = 0u;
        __syncthreads();
        unsigned prefix = s_prefix;
        unsigned highmask = (pass == 3) ? 0u : (0xFFFFFFFFu << (shift + 8));
        for (int i = tid; i < NPIX; i += 1024) {
            unsigned u = skey[i];
            if ((u & highmask) == prefix)
                atomicAdd(&hist[(u >> shift) & 255u], 1u);
        }
        __syncthreads();
        if (tid == 0) {
            int k = s_k;
            unsigned cum = 0;
            for (int d = 255; d >= 0; --d) {
                unsigned cnt = hist[d];
                if ((unsigned)k <= cum + cnt) {
                    s_prefix = prefix | ((unsigned)d << shift);
                    s_k = k - (int)cum;
                    break;
                }
                cum += cnt;
            }
        }
        __syncthreads();
    }
    unsigned T = s_prefix;
    int ties = s_k;
    int lane = tid & 31, w = tid >> 5;
    for (int base = 0; base < NPIX; base += 1024) {
        int i = base + tid;
        unsigned u = skey[i];
        int gt = (u > T), eq = (u == T);
        unsigned ball = __ballot_sync(0xffffffffu, eq);
        int pre = __popc(ball & ((1u << lane) - 1u));
        if (lane == 0) warp_sums[w] = __popc(ball);
        __syncthreads();
        int woff = 0;
        for (int xw = 0; xw < w; ++xw) woff += warp_sums[xw];
        int rank = s_carry + woff + pre;
        g_flags[(size_t)b * NPIX + i] = (unsigned char)(gt || (eq && rank < ties));
        __syncthreads();
        if (tid == 0) {
            int tot = 0;
            for (int xw = 0; xw < 32; ++xw) tot += warp_sums[xw];
            s_carry += tot;
        }
        __syncthreads();
    }
}

// ---------------- kernel 2: fused LN + MLP, fp16, 32 tokens/warp ----------
__global__ void __launch_bounds__(NTHR, 1)
main_kernel(const float* __restrict__ x,
            const float* __restrict__ lnscale, const float* __restrict__ lnbias,
            const float* __restrict__ b1g, const float* __restrict__ b2g,
            float* __restrict__ out) {
    extern __shared__ char sm[];
    float* sT  = (float*)(sm + OFF_T);
    unsigned* sB1h = (unsigned*)(sm + OFF_B1);
    float* sB2 = (float*)(sm + OFF_B2);
    float* sLS = (float*)(sm + OFF_LS);
    float* sLB = (float*)(sm + OFF_LB);
    int*   sFlag = (int*)(sm + OFF_FLAG);
    unsigned smem_base = (unsigned)__cvta_generic_to_shared(sm);

    int tid = threadIdx.x;
    int lane = tid & 31, w = tid >> 5;
    int tb = w * 32;                 // this warp's 32 tokens
    int b = blockIdx.y, n0 = blockIdx.x * TOKB;

    int r = lane >> 2;               // fragment row within 8
    int c2 = (lane & 3) * 2;         // fragment col pair
    int r15 = lane & 15;
    int colsel = ((lane >> 4) & 1) * 8;
    int row0a = tb + r,      row1a = row0a + 8;   // M-tile A
    int row0b = tb + 16 + r, row1b = row0b + 8;   // M-tile B

    // ---- stage chunk 0 weights (async) ----
    {
        const char* s1 = (const char*)g_w1;
        const char* s2 = (const char*)g_w2;
        unsigned dst = smem_base + OFF_W;
        for (int i = tid * 16; i < 64 * W1_S * 2; i += NTHR * 16) cp16(dst + i, s1 + i);
        for (int i = tid * 16; i < 128 * W2_S * 2; i += NTHR * 16) cp16(dst + 17408 + i, s2 + i);
        asm volatile("cp.async.commit_group;");
    }

    // ---- load x tile: sT[t][c], params, flags ----
    const float* xb = x + (size_t)b * CH * NPIX + n0;
    for (int i = tid; i < TOKB * CH; i += NTHR) {
        int t = i & (TOKB - 1);
        int c = i >> 8;
        sT[t * ST_S + c] = xb[(size_t)c * NPIX + t];
    }
    if (tid < HID) sB1h[tid] = pack_h2(make_float2(b1g[2 * tid], b1g[2 * tid + 1]));
    if (tid < 2 * CH) {
        sB2[tid] = b2g[tid];
        sLS[tid] = lnscale[tid];
        sLB[tid] = lnbias[tid];
    }
    if (tid < TOKB) sFlag[tid] = g_flags[(size_t)b * NPIX + n0 + tid];
    __syncthreads();

    for (int layer = 0; layer < 2; ++layer) {
        // ---- LN stats: 1 lane per token (full 64-ch row) ----
        float mu, rs;
        {
            const float* rowp = sT + (tb + lane) * ST_S;
            float s = 0.f, s2 = 0.f;
            #pragma unroll
            for (int k = 0; k < 64; k += 4) {
                float4 v = *(const float4*)(rowp + k);
                s  += v.x + v.y + v.z + v.w;
                s2 += v.x * v.x + v.y * v.y + v.z * v.z + v.w * v.w;
            }
            mu = s * (1.f / 64.f);
            float var = s2 * (1.f / 64.f) - mu * mu;
            rs = rsqrtf(var + 1e-5f);
        }
        float mu0a = __shfl_sync(0xffffffffu, mu, r);
        float rs0a = __shfl_sync(0xffffffffu, rs, r);
        float mu1a = __shfl_sync(0xffffffffu, mu, r + 8);
        float rs1a = __shfl_sync(0xffffffffu, rs, r + 8);
        float mu0b = __shfl_sync(0xffffffffu, mu, r + 16);
        float rs0b = __shfl_sync(0xffffffffu, rs, r + 16);
        float mu1b = __shfl_sync(0xffffffffu, mu, r + 24);
        float rs1b = __shfl_sync(0xffffffffu, rs, r + 24);

        // ---- build GEMM1 A-fragments (Xn) in registers, fp16, two M-tiles ----
        unsigned aXa[16], aXb[16];
        #pragma unroll
        for (int kt = 0; kt < 4; ++kt) {
            int cA = kt * 16 + c2;
            float2 lsA = *(const float2*)(sLS + layer * 64 + cA);
            float2 lbA = *(const float2*)(sLB + layer * 64 + cA);
            float2 lsB = *(const float2*)(sLS + layer * 64 + cA + 8);
            float2 lbB = *(const float2*)(sLB + layer * 64 + cA + 8);
            float2 v;
            v = *(const float2*)(sT + row0a * ST_S + cA);
            v.x = (v.x - mu0a) * rs0a * lsA.x + lbA.x;
            v.y = (v.y - mu0a) * rs0a * lsA.y + lbA.y;
            aXa[kt * 4 + 0] = pack_h2(v);
            v = *(const float2*)(sT + row1a * ST_S + cA);
            v.x = (v.x - mu1a) * rs1a * lsA.x + lbA.x;
            v.y = (v.y - mu1a) * rs1a * lsA.y + lbA.y;
            aXa[kt * 4 + 1] = pack_h2(v);
            v = *(const float2*)(sT + row0a * ST_S + cA + 8);
            v.x = (v.x - mu0a) * rs0a * lsB.x + lbB.x;
            v.y = (v.y - mu0a) * rs0a * lsB.y + lbB.y;
            aXa[kt * 4 + 2] = pack_h2(v);
            v = *(const float2*)(sT + row1a * ST_S + cA + 8);
            v.x = (v.x - mu1a) * rs1a * lsB.x + lbB.x;
            v.y = (v.y - mu1a) * rs1a * lsB.y + lbB.y;
            aXa[kt * 4 + 3] = pack_h2(v);

            v = *(const float2*)(sT + row0b * ST_S + cA);
            v.x = (v.x - mu0b) * rs0b * lsA.x + lbA.x;
            v.y = (v.y - mu0b) * rs0b * lsA.y + lbA.y;
            aXb[kt * 4 + 0] = pack_h2(v);
            v = *(const float2*)(sT + row1b * ST_S + cA);
            v.x = (v.x - mu1b) * rs1b * lsA.x + lbA.x;
            v.y = (v.y - mu1b) * rs1b * lsA.y + lbA.y;
            aXb[kt * 4 + 1] = pack_h2(v);
            v = *(const float2*)(sT + row0b * ST_S + cA + 8);
            v.x = (v.x - mu0b) * rs0b * lsB.x + lbB.x;
            v.y = (v.y - mu0b) * rs0b * lsB.y + lbB.y;
            aXb[kt * 4 + 2] = pack_h2(v);
            v = *(const float2*)(sT + row1b * ST_S + cA + 8);
            v.x = (v.x - mu1b) * rs1b * lsB.x + lbB.x;
            v.y = (v.y - mu1b) * rs1b * lsB.y + lbB.y;
            aXb[kt * 4 + 3] = pack_h2(v);
        }

        float d2a[32], d2b[32];
        #pragma unroll
        for (int i = 0; i < 32; ++i) { d2a[i] = 0.f; d2b[i] = 0.f; }

        for (int jc = 0; jc < 2; ++jc) {
            int ch = layer * 2 + jc;
            int buf = ch & 1;
            unsigned wbase = smem_base + OFF_W + buf * BUFB;

            // ---- prefetch next chunk into other buffer ----
            if (ch + 1 < 4) {
                int nc = ch + 1;
                const char* s1 = (const char*)(g_w1 + nc * 64 * W1_S);
                const char* s2 = (const char*)(g_w2 + nc * 128 * W2_S);
                unsigned dst = smem_base + OFF_W + (buf ^ 1) * BUFB;
                for (int i = tid * 16; i < 64 * W1_S * 2; i += NTHR * 16) cp16(dst + i, s1 + i);
                for (int i = tid * 16; i < 128 * W2_S * 2; i += NTHR * 16) cp16(dst + 17408 + i, s2 + i);
                asm volatile("cp.async.commit_group;");
                asm volatile("cp.async.wait_group 1;");
            } else {
                asm volatile("cp.async.wait_group 0;");
            }
            __syncthreads();   // current chunk weights visible to all warps

            for (int jg = 0; jg < 8; ++jg) {
                // ---- GEMM1: two 16x16 M-tiles, K=64, shared B frags ----
                float d1a[8], d1b[8];
                #pragma unroll
                for (int i = 0; i < 8; ++i) { d1a[i] = 0.f; d1b[i] = 0.f; }
                #pragma unroll
                for (int kt = 0; kt < 4; ++kt) {
                    unsigned bh[4];
                    unsigned boff = (unsigned)((kt * 16 + r15) * W1_S + jg * 16 + colsel) * 2;
                    ldsm_x4t(bh, wbase + boff);
                    mma_f16(d1a,     aXa + kt * 4, bh[0], bh[1]);
                    mma_f16(d1b,     aXb + kt * 4, bh[0], bh[1]);
                    mma_f16(d1a + 4, aXa + kt * 4, bh[2], bh[3]);
                    mma_f16(d1b + 4, aXb + kt * 4, bh[2], bh[3]);
                }
                // ---- epilogue in h2: pack + bias + gelu -> GEMM2 A frags ----
                unsigned a2a[4], a2b[4];
                {
                    int j0 = jc * 128 + jg * 16;
                    int pb = (layer * HID + j0) >> 1;
                    unsigned b0 = sB1h[pb + (c2 >> 1)];
                    unsigned b8 = sB1h[pb + 4 + (c2 >> 1)];
                    __half2 b0h = *(__half2*)&b0, b8h = *(__half2*)&b8;
                    __half2 t; unsigned tu;
                    #define GEPI(dst, dd, bb) \
                        tu = pack_h2(make_float2((dd)[0], (dd)[1])); \
                        t = __hadd2(*(__half2*)&tu, bb); \
                        dst = gelu_h2(*(unsigned*)&t);
                    GEPI(a2a[0], d1a + 0, b0h); GEPI(a2a[1], d1a + 2, b0h);
                    GEPI(a2a[2], d1a + 4, b8h); GEPI(a2a[3], d1a + 6, b8h);
                    GEPI(a2b[0], d1b + 0, b0h); GEPI(a2b[1], d1b + 2, b0h);
                    GEPI(a2b[2], d1b + 4, b8h); GEPI(a2b[3], d1b + 6, b8h);
                    #undef GEPI
                }
                // ---- wait: d1 regs consumed via a2; now GEMM2 ----
                #pragma unroll
                for (int np = 0; np < 4; ++np) {
                    unsigned bh[4];
                    unsigned boff = (unsigned)((jg * 16 + r15) * W2_S + np * 16 + colsel) * 2;
                    ldsm_x4t(bh, wbase + 17408 + boff);
                    mma_f16(d2a + np * 8,     a2a, bh[0], bh[1]);
                    mma_f16(d2b + np * 8,     a2b, bh[0], bh[1]);
                    mma_f16(d2a + np * 8 + 4, a2a, bh[2], bh[3]);
                    mma_f16(d2b + np * 8 + 4, a2b, bh[2], bh[3]);
                }
            }
            __syncthreads();   // all warps done with this buffer before next overwrite
        }

        // ---- gated residual add into sT (warp-local rows) ----
        {
            int f0a = sFlag[row0a], f1a = sFlag[row1a];
            int f0b = sFlag[row0b], f1b = sFlag[row1b];
            #pragma unroll
            for (int nt = 0; nt < 8; ++nt) {
                int c0 = nt * 8 + c2;
                float2 bv = *(const float2*)(sB2 + layer * 64 + c0);
                if (f0a) {
                    sT[row0a * ST_S + c0]     += d2a[nt * 4 + 0] + bv.x;
                    sT[row0a * ST_S + c0 + 1] += d2a[nt * 4 + 1] + bv.y;
                }
                if (f1a) {
                    sT[row1a * ST_S + c0]     += d2a[nt * 4 + 2] + bv.x;
                    sT[row1a * ST_S + c0 + 1] += d2a[nt * 4 + 3] + bv.y;
                }
                if (f0b) {
                    sT[row0b * ST_S + c0]     += d2b[nt * 4 + 0] + bv.x;
                    sT[row0b * ST_S + c0 + 1] += d2b[nt * 4 + 1] + bv.y;
                }
                if (f1b) {
                    sT[row1b * ST_S + c0]     += d2b[nt * 4 + 2] + bv.x;
                    sT[row1b * ST_S + c0 + 1] += d2b[nt * 4 + 3] + bv.y;
                }
            }
        }
        __syncwarp();
    }

    // ---- store tile ----
    __syncthreads();
    float* ob = out + (size_t)b * CH * NPIX + n0;
    for (int i = tid; i < TOKB * CH; i += NTHR) {
        int t = i & (TOKB - 1);
        int c = i >> 8;
        ob[(size_t)c * NPIX + t] = sT[t * ST_S + c];
    }
}

// ---------------- launch ----------------
extern "C" void kernel_launch(void* const* d_in, const int* in_sizes, int n_in,
                              void* d_out, int out_size) {
    const float* x    = (const float*)d_in[0];
    const float* prop = (const float*)d_in[1];
    const float* lns  = (const float*)d_in[2];
    const float* lnb  = (const float*)d_in[3];
    const float* w1   = (const float*)d_in[4];
    const float* b1   = (const float*)d_in[5];
    const float* w2   = (const float*)d_in[6];
    const float* b2   = (const float*)d_in[7];
    float* out = (float*)d_out;

    cudaFuncSetAttribute(main_kernel, cudaFuncAttributeMaxDynamicSharedMemorySize, SMEM_BYTES);
    int sel_smem = (NPIX + 260) * 4;
    cudaFuncSetAttribute(select_flags_kernel, cudaFuncAttributeMaxDynamicSharedMemorySize, sel_smem);

    prep_kernel<<<64, 512>>>(w1, w2);
    select_flags_kernel<<<BATCH, 1024, sel_smem>>>(prop);
    dim3 grid(NPIX / TOKB, BATCH);
    main_kernel<<<grid, NTHR, SMEM_BYTES>>>(x, lns, lnb, b1, b2, out);
}

// round 9
// speedup vs baseline: 1.2950x; 1.2950x over previous
#include <cuda_runtime.h>
#include <cuda_fp16.h>
#include <math.h>

#define BATCH 16
#define CH    64
#define NPIX  25600          // 160*160
#define HID   256
#define KSEL  20480          // ceil(25600*0.8)
#define TOKB  128            // tokens per block
#define NTHR  256            // 8 warps

#define ST_S  68             // sT fp32 row stride (272B)
#define W1_S  136            // fp16 elements per row (272B), chunk rows=64
#define W2_S  72             // fp16 elements per row (144B), chunk rows=128

// smem byte offsets (main kernel)
#define OFF_T    0            // 128*68*4  = 34816
#define OFF_W    34816        // two chunk buffers, each 35840 (W1 17408 + W2 18432)
#define BUFB     35840
#define OFF_B1   106496       // 256 u32 (h2-packed bias1)
#define OFF_B2   108544       // 2*64*4  = 512
#define OFF_LS   109056       // 512
#define OFF_LB   109568       // 512
#define OFF_FLAG 110080       // 128*4   = 512
#define SMEM_BYTES 110592

// ---------------- static scratch ----------------
__device__ unsigned      g_thresh[BATCH];
__device__ int           g_ties[BATCH];
__device__ unsigned char g_flags[BATCH * NPIX];
// pre-converted fp16 weights in smem tile layout (chunk = layer*2 + jc)
__device__ unsigned short g_w1[4 * 64 * W1_S];
__device__ unsigned short g_w2[4 * 128 * W2_S];

__device__ __forceinline__ unsigned fkey(float f) {
    unsigned u = __float_as_uint(f);
    return (u & 0x80000000u) ? ~u : (u | 0x80000000u);
}

__device__ __forceinline__ unsigned pack_h2(float2 v) {
    __half2 h = __float22half2_rn(v);
    return *(unsigned*)&h;
}

// gelu on a packed half2 (tanh approximation, all-fp16 math)
__device__ __forceinline__ unsigned gelu_h2(unsigned vu) {
    __half2 v = *(__half2*)&vu;
    const __half2 k0  = __floats2half2_rn(0.7978845608f, 0.7978845608f);
    const __half2 k01 = __floats2half2_rn(0.0356774081f, 0.0356774081f);  // k0*0.044715
    const __half2 hf  = __floats2half2_rn(0.5f, 0.5f);
    __half2 u = __hmul2(v, v);
    __half2 w = __hmul2(u, v);
    __half2 inner = __hfma2(w, k01, __hmul2(v, k0));
    unsigned tin = *(unsigned*)&inner, tout;
    asm("tanh.approx.f16x2 %0, %1;" : "=r"(tout) : "r"(tin));
    __half2 t = *(__half2*)&tout;
    __half2 hv = __hmul2(v, hf);
    __half2 res = __hfma2(hv, t, hv);
    return *(unsigned*)&res;
}

__device__ __forceinline__ void ldsm_x4t(unsigned* r, unsigned addr) {
    asm volatile("ldmatrix.sync.aligned.m8n8.x4.trans.shared.b16 {%0,%1,%2,%3}, [%4];"
                 : "=r"(r[0]), "=r"(r[1]), "=r"(r[2]), "=r"(r[3]) : "r"(addr));
}
__device__ __forceinline__ void mma_f16(float* d, const unsigned* a, unsigned b0, unsigned b1) {
    asm volatile("mma.sync.aligned.m16n8k16.row.col.f32.f16.f16.f32 "
                 "{%0,%1,%2,%3}, {%4,%5,%6,%7}, {%8,%9}, {%0,%1,%2,%3};"
                 : "+f"(d[0]), "+f"(d[1]), "+f"(d[2]), "+f"(d[3])
                 : "r"(a[0]), "r"(a[1]), "r"(a[2]), "r"(a[3]), "r"(b0), "r"(b1));
}
__device__ __forceinline__ void cp16(unsigned dst, const void* src) {
    asm volatile("cp.async.cg.shared.global [%0], [%1], 16;" :: "r"(dst), "l"(src));
}

// ---------------- kernel 0: pre-convert weights to fp16 (smem tile layout) --------
__global__ void prep_kernel(const float* __restrict__ w1, const float* __restrict__ w2) {
    int idx = blockIdx.x * blockDim.x + threadIdx.x;
    if (idx >= 2 * CH * HID) return;
    int layer = idx >> 14;
    int rem = idx & 16383;
    {   // w1: [layer][c][j]
        int c = rem >> 8, j = rem & 255;
        __half h = __float2half_rn(w1[idx]);
        int off = (layer * 2 + (j >> 7)) * 64 * W1_S + c * W1_S + (j & 127);
        g_w1[off] = *(unsigned short*)&h;
    }
    {   // w2: [layer][j][c]
        int j = rem >> 6, c = rem & 63;
        __half h = __float2half_rn(w2[idx]);
        int off = (layer * 2 + (j >> 7)) * 128 * W2_S + (j & 127) * W2_S + c;
        g_w2[off] = *(unsigned short*)&h;
    }
}

// ---------------- kernel 1: fused per-batch radix select + flags ----------------
__global__ void select_flags_kernel(const float* __restrict__ prop) {
    int b = blockIdx.x;
    const float* p = prop + (size_t)b * NPIX;
    extern __shared__ unsigned dyn[];
    unsigned* skey = dyn;              // 25600 keys
    unsigned* hist = dyn + NPIX;       // 256
    __shared__ unsigned s_prefix;
    __shared__ int s_k;
    __shared__ int s_carry;
    __shared__ int warp_sums[32];
    int tid = threadIdx.x;
    if (tid == 0) { s_prefix = 0u; s_k = KSEL; s_carry = 0; }
    for (int i = tid; i < NPIX; i += 1024) skey[i] = fkey(p[i]);
    __syncthreads();

    for (int pass = 3; pass >= 0; --pass) {
        int shift = pass * 8;
        if (tid < 256) hist[tid] = 0u;
        __syncthreads();
        unsigned prefix = s_prefix;
        unsigned highmask = (pass == 3) ? 0u : (0xFFFFFFFFu << (shift + 8));
        for (int i = tid; i < NPIX; i += 1024) {
            unsigned u = skey[i];
            if ((u & highmask) == prefix)
                atomicAdd(&hist[(u >> shift) & 255u], 1u);
        }
        __syncthreads();
        if (tid == 0) {
            int k = s_k;
            unsigned cum = 0;
            for (int d = 255; d >= 0; --d) {
                unsigned cnt = hist[d];
                if ((unsigned)k <= cum + cnt) {
                    s_prefix = prefix | ((unsigned)d << shift);
                    s_k = k - (int)cum;
                    break;
                }
                cum += cnt;
            }
        }
        __syncthreads();
    }
    unsigned T = s_prefix;
    int ties = s_k;
    int lane = tid & 31, w = tid >> 5;
    for (int base = 0; base < NPIX; base += 1024) {
        int i = base + tid;
        unsigned u = skey[i];
        int gt = (u > T), eq = (u == T);
        unsigned ball = __ballot_sync(0xffffffffu, eq);
        int pre = __popc(ball & ((1u << lane) - 1u));
        if (lane == 0) warp_sums[w] = __popc(ball);
        __syncthreads();
        int woff = 0;
        for (int xw = 0; xw < w; ++xw) woff += warp_sums[xw];
        int rank = s_carry + woff + pre;
        g_flags[(size_t)b * NPIX + i] = (unsigned char)(gt || (eq && rank < ties));
        __syncthreads();
        if (tid == 0) {
            int tot = 0;
            for (int xw = 0; xw < 32; ++xw) tot += warp_sums[xw];
            s_carry += tot;
        }
        __syncthreads();
    }
}

// ---------------- kernel 2: fused LN + MLP, fp16, software-pipelined ldsm ----------
__global__ void __launch_bounds__(NTHR, 2)
main_kernel(const float* __restrict__ x,
            const float* __restrict__ lnscale, const float* __restrict__ lnbias,
            const float* __restrict__ b1g, const float* __restrict__ b2g,
            float* __restrict__ out) {
    extern __shared__ char sm[];
    float* sT  = (float*)(sm + OFF_T);
    unsigned* sB1h = (unsigned*)(sm + OFF_B1);
    float* sB2 = (float*)(sm + OFF_B2);
    float* sLS = (float*)(sm + OFF_LS);
    float* sLB = (float*)(sm + OFF_LB);
    int*   sFlag = (int*)(sm + OFF_FLAG);
    unsigned smem_base = (unsigned)__cvta_generic_to_shared(sm);

    int tid = threadIdx.x;
    int lane = tid & 31, w = tid >> 5;
    int tb = w * 16;
    int b = blockIdx.y, n0 = blockIdx.x * TOKB;

    int r = lane >> 2;           // fragment row within 8
    int c2 = (lane & 3) * 2;     // fragment col pair
    int r15 = lane & 15;
    int colsel = ((lane >> 4) & 1) * 8;
    int row0 = tb + r, row1 = row0 + 8;

    // ---- stage chunk 0 weights (async) ----
    {
        const char* s1 = (const char*)g_w1;
        const char* s2 = (const char*)g_w2;
        unsigned dst = smem_base + OFF_W;
        for (int i = tid * 16; i < 64 * W1_S * 2; i += NTHR * 16) cp16(dst + i, s1 + i);
        for (int i = tid * 16; i < 128 * W2_S * 2; i += NTHR * 16) cp16(dst + 17408 + i, s2 + i);
        asm volatile("cp.async.commit_group;");
    }

    // ---- load x tile: sT[t][c], params, flags ----
    const float* xb = x + (size_t)b * CH * NPIX + n0;
    for (int i = tid; i < TOKB * CH; i += NTHR) {
        int t = i & (TOKB - 1);
        int c = i >> 7;
        sT[t * ST_S + c] = xb[(size_t)c * NPIX + t];
    }
    if (tid < HID) sB1h[tid] = pack_h2(make_float2(b1g[2 * tid], b1g[2 * tid + 1]));
    if (tid < 2 * CH) {
        sB2[tid] = b2g[tid];
        sLS[tid] = lnscale[tid];
        sLB[tid] = lnbias[tid];
    }
    if (tid < TOKB) sFlag[tid] = g_flags[(size_t)b * NPIX + n0 + tid];
    __syncthreads();

    for (int layer = 0; layer < 2; ++layer) {
        // ---- LN stats (warp-local): 2 lanes per token ----
        float mu, rs;
        {
            int t = tb + (lane >> 1), half = lane & 1;
            const float* rowp = sT + t * ST_S + half * 32;
            float s = 0.f, s2 = 0.f;
            #pragma unroll
            for (int k = 0; k < 32; k += 4) {
                float4 v = *(const float4*)(rowp + k);
                s  += v.x + v.y + v.z + v.w;
                s2 += v.x * v.x + v.y * v.y + v.z * v.z + v.w * v.w;
            }
            s  += __shfl_xor_sync(0xffffffffu, s, 1);
            s2 += __shfl_xor_sync(0xffffffffu, s2, 1);
            mu = s * (1.f / 64.f);
            float var = s2 * (1.f / 64.f) - mu * mu;
            rs = rsqrtf(var + 1e-5f);
        }
        float mu0 = __shfl_sync(0xffffffffu, mu, r << 1);
        float rs0 = __shfl_sync(0xffffffffu, rs, r << 1);
        float mu1 = __shfl_sync(0xffffffffu, mu, (r << 1) + 16);
        float rs1 = __shfl_sync(0xffffffffu, rs, (r << 1) + 16);

        // ---- build GEMM1 A-fragments (Xn) in registers, fp16 ----
        unsigned aX[16];
        #pragma unroll
        for (int kt = 0; kt < 4; ++kt) {
            int cA = kt * 16 + c2;
            float2 lsA = *(const float2*)(sLS + layer * 64 + cA);
            float2 lbA = *(const float2*)(sLB + layer * 64 + cA);
            float2 lsB = *(const float2*)(sLS + layer * 64 + cA + 8);
            float2 lbB = *(const float2*)(sLB + layer * 64 + cA + 8);
            float2 v;
            v = *(const float2*)(sT + row0 * ST_S + cA);
            v.x = (v.x - mu0) * rs0 * lsA.x + lbA.x;
            v.y = (v.y - mu0) * rs0 * lsA.y + lbA.y;
            aX[kt * 4 + 0] = pack_h2(v);
            v = *(const float2*)(sT + row1 * ST_S + cA);
            v.x = (v.x - mu1) * rs1 * lsA.x + lbA.x;
            v.y = (v.y - mu1) * rs1 * lsA.y + lbA.y;
            aX[kt * 4 + 1] = pack_h2(v);
            v = *(const float2*)(sT + row0 * ST_S + cA + 8);
            v.x = (v.x - mu0) * rs0 * lsB.x + lbB.x;
            v.y = (v.y - mu0) * rs0 * lsB.y + lbB.y;
            aX[kt * 4 + 2] = pack_h2(v);
            v = *(const float2*)(sT + row1 * ST_S + cA + 8);
            v.x = (v.x - mu1) * rs1 * lsB.x + lbB.x;
            v.y = (v.y - mu1) * rs1 * lsB.y + lbB.y;
            aX[kt * 4 + 3] = pack_h2(v);
        }

        float d2[32];
        #pragma unroll
        for (int i = 0; i < 32; ++i) d2[i] = 0.f;

        for (int jc = 0; jc < 2; ++jc) {
            int ch = layer * 2 + jc;
            int buf = ch & 1;
            unsigned wbase = smem_base + OFF_W + buf * BUFB;

            // ---- prefetch next chunk into other buffer ----
            if (ch + 1 < 4) {
                int nc = ch + 1;
                const char* s1 = (const char*)(g_w1 + nc * 64 * W1_S);
                const char* s2 = (const char*)(g_w2 + nc * 128 * W2_S);
                unsigned dst = smem_base + OFF_W + (buf ^ 1) * BUFB;
                for (int i = tid * 16; i < 64 * W1_S * 2; i += NTHR * 16) cp16(dst + i, s1 + i);
                for (int i = tid * 16; i < 128 * W2_S * 2; i += NTHR * 16) cp16(dst + 17408 + i, s2 + i);
                asm volatile("cp.async.commit_group;");
                asm volatile("cp.async.wait_group 1;");
            } else {
                asm volatile("cp.async.wait_group 0;");
            }
            __syncthreads();   // current chunk weights visible to all warps

            // ---- pipeline prologue: W1 B-frags for jg=0 ----
            unsigned bh1[16], bh2[16];
            #pragma unroll
            for (int kt = 0; kt < 4; ++kt)
                ldsm_x4t(bh1 + kt * 4, wbase + (unsigned)((kt * 16 + r15) * W1_S + colsel) * 2);

            #pragma unroll
            for (int jg = 0; jg < 8; ++jg) {
                // ---- GEMM1 MMAs with resident bh1; interleave W2 ldsm for this jg ----
                float d1[8];
                #pragma unroll
                for (int i = 0; i < 8; ++i) d1[i] = 0.f;
                #pragma unroll
                for (int kt = 0; kt < 4; ++kt) {
                    ldsm_x4t(bh2 + kt * 4,
                             wbase + 17408 + (unsigned)((jg * 16 + r15) * W2_S + kt * 16 + colsel) * 2);
                    mma_f16(d1,     aX + kt * 4, bh1[kt * 4],     bh1[kt * 4 + 1]);
                    mma_f16(d1 + 4, aX + kt * 4, bh1[kt * 4 + 2], bh1[kt * 4 + 3]);
                }
                // ---- epilogue in h2: pack + bias + gelu -> GEMM2 A frags ----
                unsigned a2[4];
                {
                    int j0 = jc * 128 + jg * 16;
                    int pb = (layer * HID + j0) >> 1;
                    unsigned b0 = sB1h[pb + (c2 >> 1)];
                    unsigned b8 = sB1h[pb + 4 + (c2 >> 1)];
                    __half2 b0h = *(__half2*)&b0, b8h = *(__half2*)&b8;
                    __half2 t; unsigned tu;
                    #define GEPI(dst, dd, bb) \
                        tu = pack_h2(make_float2((dd)[0], (dd)[1])); \
                        t = __hadd2(*(__half2*)&tu, bb); \
                        dst = gelu_h2(*(unsigned*)&t);
                    GEPI(a2[0], d1 + 0, b0h); GEPI(a2[1], d1 + 2, b0h);
                    GEPI(a2[2], d1 + 4, b8h); GEPI(a2[3], d1 + 6, b8h);
                    #undef GEPI
                }
                // ---- GEMM2 MMAs with resident bh2; interleave W1 ldsm for jg+1 ----
                int jn = (jg + 1) & 7;
                #pragma unroll
                for (int np = 0; np < 4; ++np) {
                    ldsm_x4t(bh1 + np * 4,
                             wbase + (unsigned)((np * 16 + r15) * W1_S + jn * 16 + colsel) * 2);
                    mma_f16(d2 + np * 8,     a2, bh2[np * 4],     bh2[np * 4 + 1]);
                    mma_f16(d2 + np * 8 + 4, a2, bh2[np * 4 + 2], bh2[np * 4 + 3]);
                }
            }
            __syncthreads();   // all warps done with this buffer before next overwrite
        }

        // ---- gated residual add into sT (warp-local rows) ----
        {
            int f0 = sFlag[row0], f1 = sFlag[row1];
            #pragma unroll
            for (int nt = 0; nt < 8; ++nt) {
                int c0 = nt * 8 + c2;
                float2 bv = *(const float2*)(sB2 + layer * 64 + c0);
                if (f0) {
                    sT[row0 * ST_S + c0]     += d2[nt * 4 + 0] + bv.x;
                    sT[row0 * ST_S + c0 + 1] += d2[nt * 4 + 1] + bv.y;
                }
                if (f1) {
                    sT[row1 * ST_S + c0]     += d2[nt * 4 + 2] + bv.x;
                    sT[row1 * ST_S + c0 + 1] += d2[nt * 4 + 3] + bv.y;
                }
            }
        }
        __syncwarp();
    }

    // ---- store tile ----
    __syncthreads();
    float* ob = out + (size_t)b * CH * NPIX + n0;
    for (int i = tid; i < TOKB * CH; i += NTHR) {
        int t = i & (TOKB - 1);
        int c = i >> 7;
        ob[(size_t)c * NPIX + t] = sT[t * ST_S + c];
    }
}

// ---------------- launch ----------------
extern "C" void kernel_launch(void* const* d_in, const int* in_sizes, int n_in,
                              void* d_out, int out_size) {
    const float* x    = (const float*)d_in[0];
    const float* prop = (const float*)d_in[1];
    const float* lns  = (const float*)d_in[2];
    const float* lnb  = (const float*)d_in[3];
    const float* w1   = (const float*)d_in[4];
    const float* b1   = (const float*)d_in[5];
    const float* w2   = (const float*)d_in[6];
    const float* b2   = (const float*)d_in[7];
    float* out = (float*)d_out;

    cudaFuncSetAttribute(main_kernel, cudaFuncAttributeMaxDynamicSharedMemorySize, SMEM_BYTES);
    int sel_smem = (NPIX + 260) * 4;
    cudaFuncSetAttribute(select_flags_kernel, cudaFuncAttributeMaxDynamicSharedMemorySize, sel_smem);

    prep_kernel<<<64, 512>>>(w1, w2);
    select_flags_kernel<<<BATCH, 1024, sel_smem>>>(prop);
    dim3 grid(NPIX / TOKB, BATCH);
    main_kernel<<<grid, NTHR, SMEM_BYTES>>>(x, lns, lnb, b1, b2, out);
}